// round 4
// baseline (speedup 1.0000x reference)
#include <cuda_runtime.h>
#include <cstdint>

// Problem constants
#define N_NODES 400
#define NM1     399                   // N_NODES - 1
#define E_EDGES (N_NODES * NM1)       // 159600
#define PAIRS   (E_EDGES / 2)         // 79800 float4 per batch image
#define BATCH   32
#define HALFB   16                    // batches per path
#define BATCH_F4 ((size_t)PAIRS)      // float4 per batch image
#define BATCH_BYTES (E_EDGES * 2 * 4) // 1,276,800 bytes per batch image

#define THREADS 256
#define NBLKX   312                   // ceil(79800/256)
#define CHUNK   256                   // pairs per block (1 per thread)

// Dual-path store experiment: the [E,2] one-hot pattern is batch-invariant.
//  y==0 blocks: compute float4 in registers, STG.128-broadcast to batches 0..15
//               (saturates the LSU store path).
//  y==1 blocks: compute float4 into SMEM, cp.async.bulk-broadcast to batches
//               16..31 (saturates the TMA bulk-store engine).
// If the two paths have independent drain queues below the LTS cap, they add.
__device__ __forceinline__ float4 edge_pair_value(int pair,
                                                  const float* __restrict__ adj) {
    const int e0 = pair * 2;
    const int e1 = e0 + 1;
    // send = e / 399 ; k = e % 399 ; rec = k + (k >= send)
    const int s0 = e0 / NM1;
    const int k0 = e0 - s0 * NM1;
    const int r0 = k0 + (k0 >= s0 ? 1 : 0);
    const int s1 = e1 / NM1;
    const int k1 = e1 - s1 * NM1;
    const int r1 = k1 + (k1 >= s1 ? 1 : 0);
    const float a0 = __ldg(&adj[s0 * N_NODES + r0]);
    const float a1 = __ldg(&adj[s1 * N_NODES + r1]);
    const float t0 = (a0 != 0.0f) ? 1.0f : 0.0f;
    const float t1 = (a1 != 0.0f) ? 1.0f : 0.0f;
    return make_float4(1.0f - t0, t0, 1.0f - t1, t1);
}

__global__ __launch_bounds__(THREADS)
void nri_edge_onehot_dual_kernel(const float* __restrict__ adj,
                                 float4* __restrict__ out) {
    __shared__ __align__(128) float4 buf[CHUNK];

    if (blockIdx.y == 0) {
        // ── Path A: LSU STG.128 broadcast, batches [0, 16) ──
        const int pair = blockIdx.x * THREADS + threadIdx.x;
        if (pair >= PAIRS) return;
        const float4 v = edge_pair_value(pair, adj);
        #pragma unroll
        for (int b = 0; b < HALFB; b++) {
            out[(size_t)b * BATCH_F4 + pair] = v;
        }
    } else {
        // ── Path B: TMA bulk store broadcast, batches [16, 32) ──
        const int start = blockIdx.x * CHUNK;
        const int count = min(CHUNK, PAIRS - start);
        if (count <= 0) return;

        const int i = threadIdx.x;
        if (i < count) {
            buf[i] = edge_pair_value(start + i, adj);
        }
        __syncthreads();
        asm volatile("fence.proxy.async.shared::cta;" ::: "memory");

        if (threadIdx.x == 0) {
            const uint32_t saddr = (uint32_t)__cvta_generic_to_shared(buf);
            const uint32_t bytes = (uint32_t)count * 16u;
            const char* base = (const char*)out + (size_t)start * 16
                             + (size_t)HALFB * BATCH_BYTES;
            #pragma unroll
            for (int b = 0; b < HALFB; b++) {
                uint64_t dst = (uint64_t)(base + (size_t)b * BATCH_BYTES);
                asm volatile(
                    "cp.async.bulk.global.shared::cta.bulk_group [%0], [%1], %2;"
                    :: "l"(dst), "r"(saddr), "r"(bytes) : "memory");
            }
            asm volatile("cp.async.bulk.commit_group;" ::: "memory");
            asm volatile("cp.async.bulk.wait_group 0;" ::: "memory");
        }
    }
}

extern "C" void kernel_launch(void* const* d_in, const int* in_sizes, int n_in,
                              void* d_out, int out_size) {
    // Input order per reference setup_inputs():
    //   0: inputs  [32,400,12,1]   (unused)
    //   1: weather [32,12,4]       (unused)
    //   2: rel_rec [E,400]         (unused — indices recovered arithmetically)
    //   3: rel_send[E,400]         (unused)
    //   4: adj_matrix [400,400]    fp32
    const float* adj = (const float*)d_in[4];
    float4* out = (float4*)d_out;

    dim3 grid(NBLKX, 2);   // y=0: STG path, y=1: TMA path
    nri_edge_onehot_dual_kernel<<<grid, THREADS>>>(adj, out);
}